// round 16
// baseline (speedup 1.0000x reference)
#include <cuda_runtime.h>
#include <cuda_fp16.h>
#include <cstdint>

#define B_   32
#define S_   128
#define T_   128
#define E_   128
#define H_   256
#define G4_  1024
#define V_   32000

typedef unsigned long long ull;

// ---------------- scratch (device globals; no allocation) ----------------
__device__ float   g_xg[(size_t)(2 * B_ * S_) * G4_];   // [8192][1024] enc then dec
// fp16 operands for tensor-core projection
__device__ __half  g_ah[(size_t)B_ * T_ * H_];          // dec_out fp16 [4096][256]
__device__ __half  g_bh[(size_t)V_ * H_];               // W_out  fp16 [32000][256]

#define SWZ128(off) ((off) ^ (((off) >> 3) & 0x70))

__device__ __forceinline__ uint32_t smem_to_u32(const void* p) {
    uint32_t a;
    asm("{ .reg .u64 t; cvta.to.shared.u64 t, %1; cvt.u32.u64 %0, t; }" : "=r"(a) : "l"(p));
    return a;
}

#define FMA2(d, a, b) asm("fma.rn.f32x2 %0, %1, %2, %0;" : "+l"(d) : "l"(a), "l"(b))

// =================== K0: fp32 -> fp16 convert ==============================
__global__ void __launch_bounds__(256) tohalf_kernel(const float* __restrict__ src,
                                                     __half* __restrict__ dst, int n4) {
    int i = blockIdx.x * 256 + threadIdx.x;
    if (i >= n4) return;
    float4 v = ((const float4*)src)[i];
    ((__half2*)dst)[2 * i]     = __floats2half2_rn(v.x, v.y);
    ((__half2*)dst)[2 * i + 1] = __floats2half2_rn(v.z, v.w);
}

// =================== K1: embedding gather + input-gate GEMM ===============
__global__ void __launch_bounds__(256, 1) xg_kernel(
    const int* __restrict__ x, const int* __restrict__ y,
    const float* __restrict__ enc_emb, const float* __restrict__ dec_emb,
    const float* __restrict__ Wih_enc, const float* __restrict__ bih_enc,
    const float* __restrict__ bhh_enc,
    const float* __restrict__ Wih_dec, const float* __restrict__ bih_dec,
    const float* __restrict__ bhh_dec)
{
    extern __shared__ float sm[];
    float4* w_s4 = (float4*)sm;                    // [256][33] float4
    float4* e_s4 = (float4*)(sm + 256 * 132);      // [32][33]
    __shared__ int tok_s[32];

    const int tid = threadIdx.x;
    const int rt = blockIdx.x >> 2;
    const int ct = blockIdx.x & 3;
    const int rowbase = rt * 32;
    const bool enc = rowbase < (B_ * S_);

    const float* Wih = enc ? Wih_enc : Wih_dec;
    const float* emb = enc ? enc_emb : dec_emb;
    const float* bih = enc ? bih_enc : bih_dec;
    const float* bhh = enc ? bhh_enc : bhh_dec;
    const int*  toks = enc ? x : y;
    const int   rb   = enc ? rowbase : rowbase - B_ * S_;

    const int g0 = ct * 256;
    const float4* W4 = (const float4*)(Wih + (size_t)g0 * E_);
    #pragma unroll
    for (int i = 0; i < 32; ++i) {
        int fi = tid + i * 256;
        int gr = fi >> 5, e4 = fi & 31;
        w_s4[gr * 33 + e4] = W4[gr * 32 + e4];
    }
    if (tid < 32) tok_s[tid] = toks[rb + tid];
    __syncthreads();

    #pragma unroll
    for (int i = 0; i < 4; ++i) {
        int fi = tid + i * 256;
        int r = fi >> 5, e4 = fi & 31;
        e_s4[r * 33 + e4] = ((const float4*)emb)[(size_t)tok_s[r] * 32 + e4];
    }
    __syncthreads();

    float acc[32];
    #pragma unroll
    for (int r = 0; r < 32; ++r) acc[r] = 0.f;

    const int c = tid;
    #pragma unroll 8
    for (int e4 = 0; e4 < 32; ++e4) {
        float4 wv = w_s4[c * 33 + e4];
        #pragma unroll
        for (int r = 0; r < 32; ++r) {
            float4 ev = e_s4[r * 33 + e4];
            acc[r] = fmaf(wv.x, ev.x, acc[r]);
            acc[r] = fmaf(wv.y, ev.y, acc[r]);
            acc[r] = fmaf(wv.z, ev.z, acc[r]);
            acc[r] = fmaf(wv.w, ev.w, acc[r]);
        }
    }
    const int g = g0 + c;
    const float bias = bih[g] + bhh[g];
    #pragma unroll
    for (int r = 0; r < 32; ++r)
        g_xg[(size_t)(rowbase + r) * G4_ + g] = acc[r] + bias;
}

// =================== K2: clustered LSTM recurrence (PULL protocol) =========
// 16 clusters x 8 CTAs; cluster owns 2 batches; CTA rank owns 32 units.
// Producers write h LOCALLY + one release-arrive per peer; consumers PULL
// peer slabs via ld.shared::cluster during compute. No copy engine anywhere.
__device__ __forceinline__ float fast_sig(float v)  { return 1.f / (1.f + __expf(-v)); }
__device__ __forceinline__ float fast_tanh(float v) {
    float e = __expf(-2.f * fabsf(v));
    float t = (1.f - e) / (1.f + e);
    return copysignf(t, v);
}

#define MBARRIER_INIT(mbar, count) \
    asm volatile("mbarrier.init.shared.b64 [%0], %1;" :: "r"((uint32_t)(mbar)), "r"((uint32_t)(count)) : "memory")
// cluster-scope acquire wait (pairs with remote release-arrive)
#define MBARRIER_WAIT_PARITY_CL(mbar, parity) do {                                      \
    uint32_t _m = (uint32_t)(mbar); uint32_t _p = (uint32_t)(parity); uint32_t _d;      \
    asm volatile("{\n\t.reg .pred p;\n\t"                                               \
        "mbarrier.try_wait.parity.acquire.cluster.shared::cta.b64 p, [%1], %2;\n\t"     \
        "selp.b32 %0, 1, 0, p;\n\t}" : "=r"(_d) : "r"(_m), "r"(_p) : "memory");         \
    if (!_d) {                                                                           \
        asm volatile("{\n\t.reg .pred P1;\n\t"                                          \
            "WL_%=:\n\t"                                                                \
            "mbarrier.try_wait.parity.acquire.cluster.shared::cta.b64 P1, [%0], %1, 0x989680;\n\t" \
            "@P1 bra.uni WD_%=;\n\t"                                                    \
            "bra.uni WL_%=;\n\t"                                                        \
            "WD_%=:\n\t}" :: "r"(_m), "r"(_p) : "memory");                              \
    } } while (0)

__device__ __forceinline__ void load_wp(ull (&wp)[2][32], const float* __restrict__ Whh,
                                        int rg, int s, int u0) {
    const int gate = rg >> 3;
    const int ub   = u0 + ((rg * 4) & 31);
    #pragma unroll
    for (int p = 0; p < 2; ++p) {
        const float4* r0 = (const float4*)(Whh + (size_t)(gate * H_ + ub + 2 * p) * H_ + s * 32);
        const float4* r1 = (const float4*)(Whh + (size_t)(gate * H_ + ub + 2 * p + 1) * H_ + s * 32);
        #pragma unroll
        for (int q = 0; q < 8; ++q) {
            float4 a = r0[q], b = r1[q];
            asm("mov.b64 %0, {%1,%2};" : "=l"(wp[p][q * 4 + 0]) : "f"(a.x), "f"(b.x));
            asm("mov.b64 %0, {%1,%2};" : "=l"(wp[p][q * 4 + 1]) : "f"(a.y), "f"(b.y));
            asm("mov.b64 %0, {%1,%2};" : "=l"(wp[p][q * 4 + 2]) : "f"(a.z), "f"(b.z));
            asm("mov.b64 %0, {%1,%2};" : "=l"(wp[p][q * 4 + 3]) : "f"(a.w), "f"(b.w));
        }
    }
}

__global__ void __launch_bounds__(256, 1) __cluster_dims__(8, 1, 1)
rec_kernel(const float* __restrict__ Whh_enc, const float* __restrict__ Whh_dec)
{
    __shared__ __align__(16) float4 h_slab[2][32];   // [parity][own unit] (b0,b0,b1,b1)
    __shared__ float  red_s[2][8][128];              // [batch][k-slice][local row]
    __shared__ ull    mb[2][8];                      // [parity][source rank], count 1

    const int tid  = threadIdx.x;
    const int s    = tid >> 5;          // warp = k-slice (32 k) = source rank s
    const int rg   = tid & 31;          // lane = row-group (4 rows)
    const int rank = blockIdx.x & 7;
    const int u0   = rank * 32;
    const int bglob0 = (blockIdx.x >> 3) * 2;

    // cell identity (tid < 64)
    const int uu = tid & 31;
    const int bb = (tid >> 5) & 1;
    const int bglob = bglob0 + bb;

    const uint32_t mb_base = smem_to_u32(&mb[0][0]);           // +parity*64 +src*8
    const uint32_t slab_a[2] = { smem_to_u32(&h_slab[0][0]), smem_to_u32(&h_slab[1][0]) };

    ull wp[2][32];
    load_wp(wp, Whh_enc, rg, s, u0);

    if (tid < 32) {   // zero both parities' own slab (step-0 h = 0)
        h_slab[0][tid] = make_float4(0.f, 0.f, 0.f, 0.f);
        h_slab[1][tid] = make_float4(0.f, 0.f, 0.f, 0.f);
    }
    float c_reg = 0.f;
    if (tid == 0) {
        #pragma unroll
        for (int r = 0; r < 8; ++r) {
            MBARRIER_INIT(mb_base + r * 8, 1);           // parity set 0
            MBARRIER_INIT(mb_base + 64 + r * 8, 1);      // parity set 1
        }
    }
    // all CTAs: slabs + mbarriers ready before any remote read/arrive
    asm volatile("barrier.cluster.arrive.aligned;" ::: "memory");
    asm volatile("barrier.cluster.wait.aligned;" ::: "memory");

    // remote address of source-s slab for both parities (uniform per warp)
    uint32_t rslab[2];
    asm("mapa.shared::cluster.u32 %0, %1, %2;" : "=r"(rslab[0]) : "r"(slab_a[0]), "r"(s));
    asm("mapa.shared::cluster.u32 %0, %1, %2;" : "=r"(rslab[1]) : "r"(slab_a[1]), "r"(s));

    int ph[2] = {0, 0};

    for (int step = 0; step < S_ + T_; ++step) {
        const bool dec  = (step >= S_);
        const int  t    = dec ? step - S_ : step;
        const int  buf  = step & 1;
        const bool last = (step == S_ + T_ - 1);

        if (step > 0) {
            // warp s waits ONLY for source s's arrival (acquire, cluster scope)
            MBARRIER_WAIT_PARITY_CL(mb_base + (uint32_t)(buf * 64 + s * 8), ph[buf]);
            ph[buf] ^= 1;
        }

        // xg prefetch (cell threads); consumed after the reduction
        float xgv[4];
        if (tid < 64) {
            const float* xg = g_xg + (dec ? (size_t)(B_ * S_) * G4_ : 0)
                            + (size_t)(bglob * S_ + t) * G4_ + u0 + uu;
            #pragma unroll
            for (int g = 0; g < 4; ++g) xgv[g] = __ldcg(&xg[g * H_]);
        }

        // split-k compute: PULL h directly from peer s's slab (DSMEM reads,
        // uniform per warp -> 1 wavefront each, pipelined with FMA)
        ull acc2[2][2];
        #pragma unroll
        for (int p = 0; p < 2; ++p)
            #pragma unroll
            for (int b = 0; b < 2; ++b)
                asm("mov.b64 %0, {%1,%1};" : "=l"(acc2[p][b]) : "f"(0.f));
        const uint32_t hrow = rslab[buf];
        #pragma unroll
        for (int kk = 0; kk < 32; ++kk) {
            ull hb0, hb1;
            asm("ld.shared::cluster.v2.b64 {%0,%1}, [%2];" : "=l"(hb0), "=l"(hb1)
                : "r"(hrow + (uint32_t)kk * 16));
            FMA2(acc2[0][0], wp[0][kk], hb0);
            FMA2(acc2[0][1], wp[0][kk], hb1);
            FMA2(acc2[1][0], wp[1][kk], hb0);
            FMA2(acc2[1][1], wp[1][kk], hb1);
        }
        // planar, conflict-free: per batch one float4 = rows [4rg..4rg+3]
        {
            float l00, h00, l01, h01, l10, h10, l11, h11;
            asm("mov.b64 {%0,%1}, %2;" : "=f"(l00), "=f"(h00) : "l"(acc2[0][0]));
            asm("mov.b64 {%0,%1}, %2;" : "=f"(l01), "=f"(h01) : "l"(acc2[0][1]));
            asm("mov.b64 {%0,%1}, %2;" : "=f"(l10), "=f"(h10) : "l"(acc2[1][0]));
            asm("mov.b64 {%0,%1}, %2;" : "=f"(l11), "=f"(h11) : "l"(acc2[1][1]));
            *(float4*)&red_s[0][s][rg * 4] = make_float4(l00, h00, l10, h10);
            *(float4*)&red_s[1][s][rg * 4] = make_float4(l01, h01, l11, h11);
        }
        __syncthreads();

        // reduce + cell + LOCAL slab write (64 cell threads)
        if (tid < 64) {
            float pre[4];
            #pragma unroll
            for (int g = 0; g < 4; ++g) {
                float sum = xgv[g];
                #pragma unroll
                for (int ss = 0; ss < 8; ++ss)
                    sum += red_s[bb][ss][g * 32 + uu];
                pre[g] = sum;
            }
            float iv = fast_sig(pre[0]);
            float fv = fast_sig(pre[1]);
            float gv = fast_tanh(pre[2]);
            float ov = fast_sig(pre[3]);
            c_reg = fv * c_reg + iv * gv;
            float hh = ov * fast_tanh(c_reg);

            if (!last) {
                ull hv2;
                asm("mov.b64 %0, {%1,%1};" : "=l"(hv2) : "f"(hh));
                const uint32_t st_addr = slab_a[buf ^ 1] + (uint32_t)uu * 16
                                       + (uint32_t)bb * 8;
                asm volatile("st.shared.b64 [%0], %1;" :: "r"(st_addr), "l"(hv2) : "memory");
            }
            if (dec) g_ah[(size_t)(bglob * T_ + t) * H_ + u0 + uu] = __float2half(hh);
        }

        if (!last) {
            if (tid < 64) {
                asm volatile("bar.sync 1, 64;" ::: "memory");   // local slab ready
                if (tid < 8) {
                    // one release-arrive per peer: signals "source=rank slab ready"
                    uint32_t mbr;
                    asm("mapa.shared::cluster.u32 %0, %1, %2;" : "=r"(mbr)
                        : "r"(mb_base + (uint32_t)((buf ^ 1) * 64 + rank * 8)), "r"(tid));
                    asm volatile(
                        "mbarrier.arrive.release.cluster.shared::cluster.b64 _, [%0];"
                        :: "r"(mbr) : "memory");
                }
            }
        }

        if (step == S_ - 1) load_wp(wp, Whh_dec, rg, s, u0);   // overlap with wait
    }
}

// =================== K3: output projection (fp16 mma.sync, 3-stage) ========
#define PROJ_SMEM (3 * 32768)

__device__ __forceinline__ void ldm_x4(uint32_t& r0, uint32_t& r1, uint32_t& r2, uint32_t& r3,
                                       uint32_t addr) {
    asm volatile("ldmatrix.sync.aligned.m8n8.x4.shared.b16 {%0,%1,%2,%3}, [%4];"
                 : "=r"(r0), "=r"(r1), "=r"(r2), "=r"(r3) : "r"(addr));
}
__device__ __forceinline__ void ldm_x2(uint32_t& r0, uint32_t& r1, uint32_t addr) {
    asm volatile("ldmatrix.sync.aligned.m8n8.x2.shared.b16 {%0,%1}, [%2];"
                 : "=r"(r0), "=r"(r1) : "r"(addr));
}
__device__ __forceinline__ void mma16816(float* d, const uint32_t* a, const uint32_t* b) {
    asm volatile(
        "mma.sync.aligned.m16n8k16.row.col.f32.f16.f16.f32 "
        "{%0,%1,%2,%3}, {%4,%5,%6,%7}, {%8,%9}, {%0,%1,%2,%3};"
        : "+f"(d[0]), "+f"(d[1]), "+f"(d[2]), "+f"(d[3])
        : "r"(a[0]), "r"(a[1]), "r"(a[2]), "r"(a[3]), "r"(b[0]), "r"(b[1]));
}

__global__ void __launch_bounds__(256, 2) proj_kernel(const float* __restrict__ bout,
                                                      float* __restrict__ out)
{
    extern __shared__ char smem[];
    const uint32_t sbase = smem_to_u32(smem);
    const int tid  = threadIdx.x;
    const int lane = tid & 31;
    const int w    = tid >> 5;
    const int wm   = w >> 2;
    const int wn   = w & 3;
    const int m0   = blockIdx.x * 128;
    const int n0   = blockIdx.y * 128;

    auto issue_chunk = [&](int c, int st) {
        const uint32_t abuf = sbase + st * 32768;
        const uint32_t bbuf = abuf + 16384;
        const __half* Ag = g_ah + (size_t)m0 * H_ + c * 64;
        const __half* Bg = g_bh + (size_t)n0 * H_ + c * 64;
        #pragma unroll
        for (int j = 0; j < 4; ++j) {
            int fi = tid + j * 256;
            int row = fi >> 3, c8 = fi & 7;
            uint32_t soff = SWZ128((uint32_t)(row * 128 + c8 * 16));
            const void* ga = (const char*)(Ag + (size_t)row * H_ + c8 * 8);
            const void* gb = (const char*)(Bg + (size_t)row * H_ + c8 * 8);
            asm volatile("cp.async.cg.shared.global [%0], [%1], 16;" :: "r"(abuf + soff), "l"(ga));
            asm volatile("cp.async.cg.shared.global [%0], [%1], 16;" :: "r"(bbuf + soff), "l"(gb));
        }
        asm volatile("cp.async.commit_group;" ::: "memory");
    };

    float acc[4][4][4];
    #pragma unroll
    for (int i = 0; i < 4; ++i)
        #pragma unroll
        for (int j = 0; j < 4; ++j)
            #pragma unroll
            for (int k = 0; k < 4; ++k) acc[i][j][k] = 0.f;

    issue_chunk(0, 0);
    issue_chunk(1, 1);
    issue_chunk(2, 2);

    const int l16 = lane & 15;
    #pragma unroll 1
    for (int c = 0; c < 4; ++c) {
        if (c == 0 || c == 1) asm volatile("cp.async.wait_group 2;" ::: "memory");
        else if (c == 2)      asm volatile("cp.async.wait_group 1;" ::: "memory");
        else                  asm volatile("cp.async.wait_group 0;" ::: "memory");
        __syncthreads();

        const uint32_t abuf = sbase + (uint32_t)(c % 3) * 32768;
        const uint32_t bbuf = abuf + 16384;

        #pragma unroll
        for (int ks = 0; ks < 4; ++ks) {
            uint32_t a[4][4], b[4][2];
            #pragma unroll
            for (int mi = 0; mi < 4; ++mi) {
                int row = wm * 64 + mi * 16 + l16;
                uint32_t off = (uint32_t)(row * 128 + ks * 32 + (lane >> 4) * 16);
                ldm_x4(a[mi][0], a[mi][1], a[mi][2], a[mi][3], abuf + SWZ128(off));
            }
            #pragma unroll
            for (int bi = 0; bi < 4; ++bi) {
                int row = wn * 32 + bi * 8 + (l16 & 7);
                uint32_t off = (uint32_t)(row * 128 + ks * 32 + (l16 >> 3) * 16);
                ldm_x2(b[bi][0], b[bi][1], bbuf + SWZ128(off));
            }
            #pragma unroll
            for (int mi = 0; mi < 4; ++mi)
                #pragma unroll
                for (int bi = 0; bi < 4; ++bi)
                    mma16816(acc[mi][bi], a[mi], b[bi]);
        }
        if (c == 0) {                 // only chunk 3 reuses a buffer (buffer 0)
            __syncthreads();
            issue_chunk(3, 0);
        }
    }

    #pragma unroll
    for (int bi = 0; bi < 4; ++bi) {
        const int col = n0 + wn * 32 + bi * 8 + (lane & 3) * 2;
        const float2 bb2 = *(const float2*)(bout + col);
        #pragma unroll
        for (int mi = 0; mi < 4; ++mi) {
            const int row = m0 + wm * 64 + mi * 16 + (lane >> 2);
            float2 v0 = make_float2(acc[mi][bi][0] + bb2.x, acc[mi][bi][1] + bb2.y);
            float2 v1 = make_float2(acc[mi][bi][2] + bb2.x, acc[mi][bi][3] + bb2.y);
            *(float2*)(out + (size_t)row * V_ + col) = v0;
            *(float2*)(out + (size_t)(row + 8) * V_ + col) = v1;
        }
    }
}

// ============================= launch ======================================
extern "C" void kernel_launch(void* const* d_in, const int* in_sizes, int n_in,
                              void* d_out, int out_size) {
    const int*   x        = (const int*)d_in[0];
    const int*   y        = (const int*)d_in[1];
    const float* enc_emb  = (const float*)d_in[2];
    const float* dec_emb  = (const float*)d_in[3];
    const float* Wih_enc  = (const float*)d_in[4];
    const float* Whh_enc  = (const float*)d_in[5];
    const float* bih_enc  = (const float*)d_in[6];
    const float* bhh_enc  = (const float*)d_in[7];
    const float* Wih_dec  = (const float*)d_in[8];
    const float* Whh_dec  = (const float*)d_in[9];
    const float* bih_dec  = (const float*)d_in[10];
    const float* bhh_dec  = (const float*)d_in[11];
    const float* Wout     = (const float*)d_in[12];
    const float* bout     = (const float*)d_in[13];
    float*       out      = (float*)d_out;

    const int XG_SMEM = (256 * 132 + 32 * 132) * 4;

    cudaFuncSetAttribute(xg_kernel,  cudaFuncAttributeMaxDynamicSharedMemorySize, XG_SMEM);
    cudaFuncSetAttribute(proj_kernel, cudaFuncAttributeMaxDynamicSharedMemorySize, PROJ_SMEM);

    __half *bh;
    cudaGetSymbolAddress((void**)&bh, g_bh);

    tohalf_kernel<<<(V_ * H_ / 4 + 255) / 256, 256>>>(Wout, bh, V_ * H_ / 4);

    xg_kernel<<<1024, 256, XG_SMEM>>>(x, y, enc_emb, dec_emb,
                                      Wih_enc, bih_enc, bhh_enc,
                                      Wih_dec, bih_dec, bhh_dec);

    rec_kernel<<<128, 256>>>(Whh_enc, Whh_dec);

    proj_kernel<<<dim3(32, V_ / 128), 256, PROJ_SMEM>>>(bout, out);
}

// round 17
// speedup vs baseline: 1.3409x; 1.3409x over previous
#include <cuda_runtime.h>
#include <cuda_fp16.h>
#include <cstdint>

#define B_   32
#define S_   128
#define T_   128
#define E_   128
#define H_   256
#define G4_  1024
#define V_   32000

typedef unsigned long long ull;

// ---------------- scratch (device globals; no allocation) ----------------
__device__ float   g_xg[(size_t)(2 * B_ * S_) * G4_];   // [8192][1024] enc then dec
// fp16 operands for tensor-core projection
__device__ __half  g_ah[(size_t)B_ * T_ * H_];          // dec_out fp16 [4096][256]
__device__ __half  g_bh[(size_t)V_ * H_];               // W_out  fp16 [32000][256]

#define SWZ128(off) ((off) ^ (((off) >> 3) & 0x70))

__device__ __forceinline__ uint32_t smem_to_u32(const void* p) {
    uint32_t a;
    asm("{ .reg .u64 t; cvta.to.shared.u64 t, %1; cvt.u32.u64 %0, t; }" : "=r"(a) : "l"(p));
    return a;
}

#define FMA2(d, a, b) asm("fma.rn.f32x2 %0, %1, %2, %0;" : "+l"(d) : "l"(a), "l"(b))

// =================== K0: fp32 -> fp16 convert ==============================
__global__ void __launch_bounds__(256) tohalf_kernel(const float* __restrict__ src,
                                                     __half* __restrict__ dst, int n4) {
    int i = blockIdx.x * 256 + threadIdx.x;
    if (i >= n4) return;
    float4 v = ((const float4*)src)[i];
    ((__half2*)dst)[2 * i]     = __floats2half2_rn(v.x, v.y);
    ((__half2*)dst)[2 * i + 1] = __floats2half2_rn(v.z, v.w);
}

// =================== K1: embedding gather + input-gate GEMM (FMA2) =========
__global__ void __launch_bounds__(256, 1) xg_kernel(
    const int* __restrict__ x, const int* __restrict__ y,
    const float* __restrict__ enc_emb, const float* __restrict__ dec_emb,
    const float* __restrict__ Wih_enc, const float* __restrict__ bih_enc,
    const float* __restrict__ bhh_enc,
    const float* __restrict__ Wih_dec, const float* __restrict__ bih_dec,
    const float* __restrict__ bhh_dec)
{
    extern __shared__ float sm[];
    float4* w_s4 = (float4*)sm;                    // [256][33] float4
    float4* e_s4 = (float4*)(sm + 256 * 132);      // [32][33]
    __shared__ int tok_s[32];

    const int tid = threadIdx.x;
    const int rt = blockIdx.x >> 2;
    const int ct = blockIdx.x & 3;
    const int rowbase = rt * 32;
    const bool enc = rowbase < (B_ * S_);

    const float* Wih = enc ? Wih_enc : Wih_dec;
    const float* emb = enc ? enc_emb : dec_emb;
    const float* bih = enc ? bih_enc : bih_dec;
    const float* bhh = enc ? bhh_enc : bhh_dec;
    const int*  toks = enc ? x : y;
    const int   rb   = enc ? rowbase : rowbase - B_ * S_;

    const int g0 = ct * 256;
    const float4* W4 = (const float4*)(Wih + (size_t)g0 * E_);
    #pragma unroll
    for (int i = 0; i < 32; ++i) {
        int fi = tid + i * 256;
        int gr = fi >> 5, e4 = fi & 31;
        w_s4[gr * 33 + e4] = W4[gr * 32 + e4];
    }
    if (tid < 32) tok_s[tid] = toks[rb + tid];
    __syncthreads();

    #pragma unroll
    for (int i = 0; i < 4; ++i) {
        int fi = tid + i * 256;
        int r = fi >> 5, e4 = fi & 31;
        e_s4[r * 33 + e4] = ((const float4*)emb)[(size_t)tok_s[r] * 32 + e4];
    }
    __syncthreads();

    const uint32_t wbase = smem_to_u32(sm);
    const uint32_t ebase = smem_to_u32(sm + 256 * 132);

    ull acc2[32];
    #pragma unroll
    for (int r = 0; r < 32; ++r)
        asm("mov.b64 %0, {%1,%1};" : "=l"(acc2[r]) : "f"(0.f));

    const int c = tid;
    #pragma unroll 2
    for (int e4 = 0; e4 < 32; ++e4) {
        ull w01, w23;
        asm("ld.shared.v2.b64 {%0,%1}, [%2];" : "=l"(w01), "=l"(w23)
            : "r"(wbase + (uint32_t)(c * 33 + e4) * 16u));
        #pragma unroll
        for (int r = 0; r < 32; ++r) {
            ull e01, e23;
            asm("ld.shared.v2.b64 {%0,%1}, [%2];" : "=l"(e01), "=l"(e23)
                : "r"(ebase + (uint32_t)(r * 33 + e4) * 16u));
            FMA2(acc2[r], w01, e01);
            FMA2(acc2[r], w23, e23);
        }
    }
    const int g = g0 + c;
    const float bias = bih[g] + bhh[g];
    #pragma unroll
    for (int r = 0; r < 32; ++r) {
        float lo, hi;
        asm("mov.b64 {%0,%1}, %2;" : "=f"(lo), "=f"(hi) : "l"(acc2[r]));
        g_xg[(size_t)(rowbase + r) * G4_ + g] = lo + hi + bias;
    }
}

// =================== K2: clustered LSTM recurrence (R13 verbatim) ==========
__device__ __forceinline__ float fast_sig(float v)  { return 1.f / (1.f + __expf(-v)); }
__device__ __forceinline__ float fast_tanh(float v) {
    float e = __expf(-2.f * fabsf(v));
    float t = (1.f - e) / (1.f + e);
    return copysignf(t, v);
}

#define MBARRIER_INIT(mbar, count) \
    asm volatile("mbarrier.init.shared.b64 [%0], %1;" :: "r"((uint32_t)(mbar)), "r"((uint32_t)(count)) : "memory")
#define MBARRIER_EXPECT_TX(mbar, tx) \
    asm volatile("mbarrier.arrive.expect_tx.shared.b64 _, [%0], %1;" :: "r"((uint32_t)(mbar)), "r"((uint32_t)(tx)) : "memory")
#define MBARRIER_WAIT_PARITY(mbar, parity) do {                                         \
    uint32_t _m = (uint32_t)(mbar); uint32_t _p = (uint32_t)(parity); uint32_t _d;      \
    asm volatile("{\n\t.reg .pred p;\n\t"                                               \
        "mbarrier.try_wait.parity.acquire.cta.shared::cta.b64 p, [%1], %2;\n\t"         \
        "selp.b32 %0, 1, 0, p;\n\t}" : "=r"(_d) : "r"(_m), "r"(_p) : "memory");         \
    if (!_d) {                                                                           \
        asm volatile("{\n\t.reg .pred P1;\n\t"                                          \
            "WL_%=:\n\t"                                                                \
            "mbarrier.try_wait.parity.acquire.cta.shared::cta.b64 P1, [%0], %1, 0x989680;\n\t" \
            "@P1 bra.uni WD_%=;\n\t"                                                    \
            "bra.uni WL_%=;\n\t"                                                        \
            "WD_%=:\n\t}" :: "r"(_m), "r"(_p) : "memory");                              \
    } } while (0)

__device__ __forceinline__ void load_wp(ull (&wp)[2][32], const float* __restrict__ Whh,
                                        int rg, int s, int u0) {
    const int gate = rg >> 3;
    const int ub   = u0 + ((rg * 4) & 31);
    #pragma unroll
    for (int p = 0; p < 2; ++p) {
        const float4* r0 = (const float4*)(Whh + (size_t)(gate * H_ + ub + 2 * p) * H_ + s * 32);
        const float4* r1 = (const float4*)(Whh + (size_t)(gate * H_ + ub + 2 * p + 1) * H_ + s * 32);
        #pragma unroll
        for (int q = 0; q < 8; ++q) {
            float4 a = r0[q], b = r1[q];
            asm("mov.b64 %0, {%1,%2};" : "=l"(wp[p][q * 4 + 0]) : "f"(a.x), "f"(b.x));
            asm("mov.b64 %0, {%1,%2};" : "=l"(wp[p][q * 4 + 1]) : "f"(a.y), "f"(b.y));
            asm("mov.b64 %0, {%1,%2};" : "=l"(wp[p][q * 4 + 2]) : "f"(a.z), "f"(b.z));
            asm("mov.b64 %0, {%1,%2};" : "=l"(wp[p][q * 4 + 3]) : "f"(a.w), "f"(b.w));
        }
    }
}

__global__ void __launch_bounds__(256, 1) __cluster_dims__(8, 1, 1)
rec_kernel(const float* __restrict__ Whh_enc, const float* __restrict__ Whh_dec)
{
    __shared__ float4 h_s[2][256];        // [buf][unit] = (b0,b0,b1,b1)
    __shared__ float  red_s[2][8][128];   // [batch][k-slice][local row]  (planar)
    __shared__ float4 stage_s[2][32];     // [parity][local unit] 512B staging slab
    __shared__ ull    mb[2][8];           // [parity][source rank]

    const int tid  = threadIdx.x;
    const int s    = tid >> 5;          // warp = k-slice (32 k) = source slab s
    const int rg   = tid & 31;          // lane = row-group (4 rows)
    const int rank = blockIdx.x & 7;
    const int u0   = rank * 32;
    const int bglob0 = (blockIdx.x >> 3) * 2;

    // cell identity (tid < 64)
    const int uu = tid & 31;
    const int bb = (tid >> 5) & 1;
    const int bglob = bglob0 + bb;

    const uint32_t mb_base    = smem_to_u32(&mb[0][0]);          // +parity*64 +src*8
    const uint32_t hbase[2]   = { smem_to_u32(&h_s[0][0]), smem_to_u32(&h_s[1][0]) };
    const uint32_t stbase[2]  = { smem_to_u32(&stage_s[0][0]), smem_to_u32(&stage_s[1][0]) };

    ull wp[2][32];
    load_wp(wp, Whh_enc, rg, s, u0);

    h_s[0][tid] = make_float4(0.f, 0.f, 0.f, 0.f);
    float c_reg = 0.f;
    if (tid == 0) {
        #pragma unroll
        for (int r = 0; r < 8; ++r) {
            MBARRIER_INIT(mb_base + r * 8, 1);           // parity-0 set
            MBARRIER_INIT(mb_base + 64 + r * 8, 1);      // parity-1 set
            MBARRIER_EXPECT_TX(mb_base + 64 + r * 8, 512u);  // covers step-0 copies
        }
    }
    // all CTAs: mbarriers + h_s[0] ready before any remote copy
    asm volatile("barrier.cluster.arrive.aligned;" ::: "memory");
    asm volatile("barrier.cluster.wait.aligned;" ::: "memory");

    int ph[2] = {0, 0};

    for (int step = 0; step < S_ + T_; ++step) {
        const bool dec  = (step >= S_);
        const int  t    = dec ? step - S_ : step;
        const int  buf  = step & 1;
        const bool last = (step == S_ + T_ - 1);

        if (step > 0) {
            // warp s waits ONLY for its slab's arrival
            MBARRIER_WAIT_PARITY(mb_base + (uint32_t)(buf * 64 + s * 8), ph[buf]);
            ph[buf] ^= 1;
            // re-arm next-parity expects (warp 0, one barrier per thread)
            if (tid < 8 && !last)
                MBARRIER_EXPECT_TX(mb_base + (uint32_t)((buf ^ 1) * 64 + tid * 8), 512u);
        }

        // xg prefetch (cell threads); consumed after the reduction
        float xgv[4];
        if (tid < 64) {
            const float* xg = g_xg + (dec ? (size_t)(B_ * S_) * G4_ : 0)
                            + (size_t)(bglob * S_ + t) * G4_ + u0 + uu;
            #pragma unroll
            for (int g = 0; g < 4; ++g) xgv[g] = __ldcg(&xg[g * H_]);
        }

        // split-k compute: fma.f32x2, W in regs, h uniform-broadcast LDS
        ull acc2[2][2];
        #pragma unroll
        for (int p = 0; p < 2; ++p)
            #pragma unroll
            for (int b = 0; b < 2; ++b)
                asm("mov.b64 %0, {%1,%1};" : "=l"(acc2[p][b]) : "f"(0.f));
        const uint32_t hrow = hbase[buf] + (uint32_t)(s * 32) * 16;
        #pragma unroll
        for (int kk = 0; kk < 32; ++kk) {
            ull hb0, hb1;
            asm("ld.shared.v2.b64 {%0,%1}, [%2];" : "=l"(hb0), "=l"(hb1)
                : "r"(hrow + (uint32_t)kk * 16));
            FMA2(acc2[0][0], wp[0][kk], hb0);
            FMA2(acc2[0][1], wp[0][kk], hb1);
            FMA2(acc2[1][0], wp[1][kk], hb0);
            FMA2(acc2[1][1], wp[1][kk], hb1);
        }
        // planar, conflict-free: per batch one float4 = rows [4rg..4rg+3]
        {
            float l00, h00, l01, h01, l10, h10, l11, h11;
            asm("mov.b64 {%0,%1}, %2;" : "=f"(l00), "=f"(h00) : "l"(acc2[0][0]));
            asm("mov.b64 {%0,%1}, %2;" : "=f"(l01), "=f"(h01) : "l"(acc2[0][1]));
            asm("mov.b64 {%0,%1}, %2;" : "=f"(l10), "=f"(h10) : "l"(acc2[1][0]));
            asm("mov.b64 {%0,%1}, %2;" : "=f"(l11), "=f"(h11) : "l"(acc2[1][1]));
            *(float4*)&red_s[0][s][rg * 4] = make_float4(l00, h00, l10, h10);
            *(float4*)&red_s[1][s][rg * 4] = make_float4(l01, h01, l11, h11);
        }
        __syncthreads();

        // reduce + cell + stage (64 cell threads)
        if (tid < 64) {
            float pre[4];
            #pragma unroll
            for (int g = 0; g < 4; ++g) {
                float sum = xgv[g];
                #pragma unroll
                for (int ss = 0; ss < 8; ++ss)
                    sum += red_s[bb][ss][g * 32 + uu];
                pre[g] = sum;
            }
            float iv = fast_sig(pre[0]);
            float fv = fast_sig(pre[1]);
            float gv = fast_tanh(pre[2]);
            float ov = fast_sig(pre[3]);
            c_reg = fv * c_reg + iv * gv;
            float hh = ov * fast_tanh(c_reg);

            if (!last) {
                ull hv2;
                asm("mov.b64 %0, {%1,%1};" : "=l"(hv2) : "f"(hh));
                const uint32_t st_addr = stbase[buf ^ 1] + (uint32_t)uu * 16
                                       + (uint32_t)bb * 8;
                asm volatile("st.shared.b64 [%0], %1;" :: "r"(st_addr), "l"(hv2) : "memory");
                asm volatile("fence.proxy.async.shared::cta;" ::: "memory");
            }
            if (dec) g_ah[(size_t)(bglob * T_ + t) * H_ + u0 + uu] = __float2half(hh);
        }

        if (!last) {
            if (tid < 64) {
                asm volatile("bar.sync 1, 64;" ::: "memory");   // stage complete
                if (tid < 8) {
                    // one 512B bulk copy to peer `tid`; target barrier = OUR rank
                    uint32_t dst, mbr;
                    asm("mapa.shared::cluster.u32 %0, %1, %2;"
                        : "=r"(dst) : "r"(hbase[buf ^ 1] + (uint32_t)u0 * 16), "r"(tid));
                    asm("mapa.shared::cluster.u32 %0, %1, %2;"
                        : "=r"(mbr)
                        : "r"(mb_base + (uint32_t)((buf ^ 1) * 64 + rank * 8)), "r"(tid));
                    asm volatile(
                        "cp.async.bulk.shared::cluster.shared::cta.mbarrier::complete_tx::bytes "
                        "[%0], [%1], %2, [%3];"
                        :: "r"(dst), "r"(stbase[buf ^ 1]), "r"(512u), "r"(mbr) : "memory");
                }
            }
        }

        if (step == S_ - 1) load_wp(wp, Whh_dec, rg, s, u0);   // overlap with wait
    }
}

// =================== K3: output projection (fp16 mma.sync, 3-stage) ========
#define PROJ_SMEM (3 * 32768)

__device__ __forceinline__ void ldm_x4(uint32_t& r0, uint32_t& r1, uint32_t& r2, uint32_t& r3,
                                       uint32_t addr) {
    asm volatile("ldmatrix.sync.aligned.m8n8.x4.shared.b16 {%0,%1,%2,%3}, [%4];"
                 : "=r"(r0), "=r"(r1), "=r"(r2), "=r"(r3) : "r"(addr));
}
__device__ __forceinline__ void ldm_x2(uint32_t& r0, uint32_t& r1, uint32_t addr) {
    asm volatile("ldmatrix.sync.aligned.m8n8.x2.shared.b16 {%0,%1}, [%2];"
                 : "=r"(r0), "=r"(r1) : "r"(addr));
}
__device__ __forceinline__ void mma16816(float* d, const uint32_t* a, const uint32_t* b) {
    asm volatile(
        "mma.sync.aligned.m16n8k16.row.col.f32.f16.f16.f32 "
        "{%0,%1,%2,%3}, {%4,%5,%6,%7}, {%8,%9}, {%0,%1,%2,%3};"
        : "+f"(d[0]), "+f"(d[1]), "+f"(d[2]), "+f"(d[3])
        : "r"(a[0]), "r"(a[1]), "r"(a[2]), "r"(a[3]), "r"(b[0]), "r"(b[1]));
}

__global__ void __launch_bounds__(256, 2) proj_kernel(const float* __restrict__ bout,
                                                      float* __restrict__ out)
{
    extern __shared__ char smem[];
    const uint32_t sbase = smem_to_u32(smem);
    const int tid  = threadIdx.x;
    const int lane = tid & 31;
    const int w    = tid >> 5;
    const int wm   = w >> 2;
    const int wn   = w & 3;
    const int m0   = blockIdx.x * 128;
    const int n0   = blockIdx.y * 128;

    auto issue_chunk = [&](int c, int st) {
        const uint32_t abuf = sbase + st * 32768;
        const uint32_t bbuf = abuf + 16384;
        const __half* Ag = g_ah + (size_t)m0 * H_ + c * 64;
        const __half* Bg = g_bh + (size_t)n0 * H_ + c * 64;
        #pragma unroll
        for (int j = 0; j < 4; ++j) {
            int fi = tid + j * 256;
            int row = fi >> 3, c8 = fi & 7;
            uint32_t soff = SWZ128((uint32_t)(row * 128 + c8 * 16));
            const void* ga = (const char*)(Ag + (size_t)row * H_ + c8 * 8);
            const void* gb = (const char*)(Bg + (size_t)row * H_ + c8 * 8);
            asm volatile("cp.async.cg.shared.global [%0], [%1], 16;" :: "r"(abuf + soff), "l"(ga));
            asm volatile("cp.async.cg.shared.global [%0], [%1], 16;" :: "r"(bbuf + soff), "l"(gb));
        }
        asm volatile("cp.async.commit_group;" ::: "memory");
    };

    float acc[4][4][4];
    #pragma unroll
    for (int i = 0; i < 4; ++i)
        #pragma unroll
        for (int j = 0; j < 4; ++j)
            #pragma unroll
            for (int k = 0; k < 4; ++k) acc[i][j][k] = 0.f;

    issue_chunk(0, 0);
    issue_chunk(1, 1);
    issue_chunk(2, 2);

    const int l16 = lane & 15;
    #pragma unroll 1
    for (int c = 0; c < 4; ++c) {
        if (c == 0 || c == 1) asm volatile("cp.async.wait_group 2;" ::: "memory");
        else if (c == 2)      asm volatile("cp.async.wait_group 1;" ::: "memory");
        else                  asm volatile("cp.async.wait_group 0;" ::: "memory");
        __syncthreads();

        const uint32_t abuf = sbase + (uint32_t)(c % 3) * 32768;
        const uint32_t bbuf = abuf + 16384;

        #pragma unroll
        for (int ks = 0; ks < 4; ++ks) {
            uint32_t a[4][4], b[4][2];
            #pragma unroll
            for (int mi = 0; mi < 4; ++mi) {
                int row = wm * 64 + mi * 16 + l16;
                uint32_t off = (uint32_t)(row * 128 + ks * 32 + (lane >> 4) * 16);
                ldm_x4(a[mi][0], a[mi][1], a[mi][2], a[mi][3], abuf + SWZ128(off));
            }
            #pragma unroll
            for (int bi = 0; bi < 4; ++bi) {
                int row = wn * 32 + bi * 8 + (l16 & 7);
                uint32_t off = (uint32_t)(row * 128 + ks * 32 + (l16 >> 3) * 16);
                ldm_x2(b[bi][0], b[bi][1], bbuf + SWZ128(off));
            }
            #pragma unroll
            for (int mi = 0; mi < 4; ++mi)
                #pragma unroll
                for (int bi = 0; bi < 4; ++bi)
                    mma16816(acc[mi][bi], a[mi], b[bi]);
        }
        if (c == 0) {                 // only chunk 3 reuses a buffer (buffer 0)
            __syncthreads();
            issue_chunk(3, 0);
        }
    }

    #pragma unroll
    for (int bi = 0; bi < 4; ++bi) {
        const int col = n0 + wn * 32 + bi * 8 + (lane & 3) * 2;
        const float2 bb2 = *(const float2*)(bout + col);
        #pragma unroll
        for (int mi = 0; mi < 4; ++mi) {
            const int row = m0 + wm * 64 + mi * 16 + (lane >> 2);
            float2 v0 = make_float2(acc[mi][bi][0] + bb2.x, acc[mi][bi][1] + bb2.y);
            float2 v1 = make_float2(acc[mi][bi][2] + bb2.x, acc[mi][bi][3] + bb2.y);
            *(float2*)(out + (size_t)row * V_ + col) = v0;
            *(float2*)(out + (size_t)(row + 8) * V_ + col) = v1;
        }
    }
}

// ============================= launch ======================================
extern "C" void kernel_launch(void* const* d_in, const int* in_sizes, int n_in,
                              void* d_out, int out_size) {
    const int*   x        = (const int*)d_in[0];
    const int*   y        = (const int*)d_in[1];
    const float* enc_emb  = (const float*)d_in[2];
    const float* dec_emb  = (const float*)d_in[3];
    const float* Wih_enc  = (const float*)d_in[4];
    const float* Whh_enc  = (const float*)d_in[5];
    const float* bih_enc  = (const float*)d_in[6];
    const float* bhh_enc  = (const float*)d_in[7];
    const float* Wih_dec  = (const float*)d_in[8];
    const float* Whh_dec  = (const float*)d_in[9];
    const float* bih_dec  = (const float*)d_in[10];
    const float* bhh_dec  = (const float*)d_in[11];
    const float* Wout     = (const float*)d_in[12];
    const float* bout     = (const float*)d_in[13];
    float*       out      = (float*)d_out;

    const int XG_SMEM = (256 * 132 + 32 * 132) * 4;

    cudaFuncSetAttribute(xg_kernel,  cudaFuncAttributeMaxDynamicSharedMemorySize, XG_SMEM);
    cudaFuncSetAttribute(proj_kernel, cudaFuncAttributeMaxDynamicSharedMemorySize, PROJ_SMEM);

    __half *bh;
    cudaGetSymbolAddress((void**)&bh, g_bh);

    tohalf_kernel<<<(V_ * H_ / 4 + 255) / 256, 256>>>(Wout, bh, V_ * H_ / 4);

    xg_kernel<<<1024, 256, XG_SMEM>>>(x, y, enc_emb, dec_emb,
                                      Wih_enc, bih_enc, bhh_enc,
                                      Wih_dec, bih_dec, bhh_dec);

    rec_kernel<<<128, 256>>>(Whh_enc, Whh_dec);

    proj_kernel<<<dim3(32, V_ / 128), 256, PROJ_SMEM>>>(bout, out);
}